// round 15
// baseline (speedup 1.0000x reference)
#include <cuda_runtime.h>
#include <cuda_fp16.h>
#include <math.h>
#include <stdint.h>

// Problem constants
#define BATCH 8
#define HW 56
#define NPIX 3136
#define CMID 32
#define CXV 512             // cout*8
#define CU 256              // cmid*8
#define KIN 512             // GEMM K
#define MROWS 768           // 512 xv + 256 u

// ---- device scratch (no allocation allowed) ----
__device__ __half g_Wh[MROWS * KIN];                // [m][k] row-major fp16
__device__ float g_xv[(size_t)BATCH * CXV * NPIX];
__device__ float g_u[(size_t)BATCH * CU * NPIX];
// GN partials written by GEMM: [b][bm-4][bx(25)][i_local(16)][{sum,sumsq}]
__device__ float g_part2[BATCH][2][25][16][2];

__constant__ int c_perm[8][8] = {
    {0, 1, 2, 3, 4, 5, 6, 7},
    {3, 0, 1, 2, 5, 6, 7, 4},
    {2, 3, 0, 1, 6, 7, 4, 5},
    {1, 2, 3, 0, 7, 4, 5, 6},
    {4, 5, 6, 7, 0, 1, 2, 3},
    {5, 6, 7, 4, 3, 0, 1, 2},
    {6, 7, 4, 5, 2, 3, 0, 1},
    {7, 4, 5, 6, 1, 2, 3, 0},
};
__constant__ int c_tap[8][9] = {
    {0,1,2,3,4,5,6,7,8},
    {2,5,8,1,4,7,0,3,6},
    {8,7,6,5,4,3,2,1,0},
    {6,3,0,7,4,1,8,5,2},
    {2,1,0,5,4,3,8,7,6},
    {8,5,2,7,4,1,6,3,0},
    {6,7,8,3,4,5,0,1,2},
    {0,3,6,1,4,7,2,5,8},
};

__device__ __forceinline__ uint32_t smem_u32(const void* p) {
    uint32_t a;
    asm("{ .reg .u64 t; cvta.to.shared.u64 t, %1; cvt.u32.u64 %0, t; }" : "=r"(a) : "l"(p));
    return a;
}
__device__ __forceinline__ void ldsm_x4(uint32_t* r, uint32_t addr) {
    asm volatile("ldmatrix.sync.aligned.m8n8.x4.shared.b16 {%0,%1,%2,%3}, [%4];"
                 : "=r"(r[0]), "=r"(r[1]), "=r"(r[2]), "=r"(r[3]) : "r"(addr));
}
__device__ __forceinline__ void ldsm_x4_t(uint32_t* r, uint32_t addr) {
    asm volatile("ldmatrix.sync.aligned.m8n8.x4.trans.shared.b16 {%0,%1,%2,%3}, [%4];"
                 : "=r"(r[0]), "=r"(r[1]), "=r"(r[2]), "=r"(r[3]) : "r"(addr));
}
__device__ __forceinline__ void mma16816(float* c, const uint32_t* a, const uint32_t* b) {
    asm volatile("mma.sync.aligned.m16n8k16.row.col.f32.f16.f16.f32 "
                 "{%0,%1,%2,%3}, {%4,%5,%6,%7}, {%8,%9}, {%0,%1,%2,%3};"
                 : "+f"(c[0]), "+f"(c[1]), "+f"(c[2]), "+f"(c[3])
                 : "r"(a[0]), "r"(a[1]), "r"(a[2]), "r"(a[3]), "r"(b[0]), "r"(b[1]));
}
__device__ __forceinline__ uint32_t pack_h2(float a, float b) {
    __half2 h = __floats2half2_rn(a, b);
    return *(uint32_t*)&h;
}
#define CP16(dst, src) \
    asm volatile("cp.async.cg.shared.global [%0], [%1], 16;" :: "r"(dst), "l"(src))
#define CPCOMMIT() asm volatile("cp.async.commit_group;")
#define CPWAIT1() asm volatile("cp.async.wait_group 1;")
#define CPWAIT0() asm volatile("cp.async.wait_group 0;")

// gemm smem: A 3 stages x 10240 (128 rows x 80B); B 2 buffers x [32][136] fp16
#define S_AH 0
#define S_B 30720
#define BS_PITCH 136
#define BS_SIZE (32 * BS_PITCH * 2)   // 8704
#define S_TOTAL (S_B + 2 * BS_SIZE)   // 48128

// epi dynamic smem (float offsets); plane-major xs
#define E_XS 0                   // float4[4][6][58] = 5568 floats
#define E_TH 5568                // [36][224] = 8064
#define E_W2T 13632              // [32][40] = 1280
#define E_B2 14912               // [40]
#define E_GN 14952               // [32][4] = 128
#define E_FLOATS 15080
#define E_BYTES (E_FLOATS * 4)   // 60320

// ---------------------------------------------------------------------------
// Kernel 0: expand W -> fp16 [m][k] row-major
// ---------------------------------------------------------------------------
__global__ void expand_w_kernel(const float* __restrict__ w_v,
                                const float* __restrict__ w1) {
    int idx = blockIdx.x * 256 + threadIdx.x;
    if (idx >= MROWS * KIN) return;
    int m = idx >> 9, k = idx & 511;
    int i = k >> 3, f = k & 7;
    float val;
    if (m < 512) {
        int o = m >> 3, g = m & 7;
        val = w_v[(o * 64 + i) * 8 + c_perm[g][f]];
    } else {
        int m2 = m - 512;
        int o = m2 >> 3, g = m2 & 7;
        val = w1[(o * 64 + i) * 8 + c_perm[g][f]];
    }
    g_Wh[idx] = __float2half_rn(val);
}

// ---------------------------------------------------------------------------
// Kernel 1: fp16 mma.sync GEMM reading x DIRECTLY (fp32 -> fp16 in-kernel,
// B consumed untransposed via ldmatrix.trans). Fused GN partial stats.
// tile 128M x 128N, 256 thr (8 warps 4Mx2N), BK=32.
// ---------------------------------------------------------------------------
__global__ __launch_bounds__(256, 2) void gemm_mma_kernel(const float* __restrict__ x) {
    extern __shared__ char sm[];
    __shared__ float red[8][4][2];   // [wid][ms*2+half][{s,s2}]
    const uint32_t sb = smem_u32(sm);
    const int tid = threadIdx.x;
    const int lane = tid & 31, wid = tid >> 5;
    const int warpM = wid >> 1, warpN = wid & 1;
    const int bx = blockIdx.x, bm = blockIdx.y, bb = blockIdx.z;
    const int n0 = bx * 128;

    // ---- A: cp.async 3-stage (unchanged) ----
    const char* __restrict__ gAh = (const char*)g_Wh + (size_t)bm * 128 * 1024;
    const int ar = tid >> 1, ag = (tid & 1) * 32;
#define ISSUE_A(ck, s) do { \
        const char* a0 = gAh + (size_t)ar * 1024 + (ck) * 64 + ag; \
        uint32_t da0 = sb + S_AH + (s) * 10240 + ar * 80 + ag; \
        CP16(da0, a0); CP16(da0 + 16, a0 + 16); \
        CPCOMMIT(); \
    } while (0)

    // ---- B: register prefetch of fp32 x, convert -> fp16 [k][n] tile ----
    const int bkr = tid >> 3;                 // k-row 0..31
    const int bns = (tid & 7) * 16;           // n-offset within tile
    int bcol = n0 + bns;
    if (bcol > NPIX - 16) bcol = NPIX - 16;   // clamp (edge block; outputs discarded)
    const float* __restrict__ gx =
        x + ((size_t)bb * KIN + bkr) * NPIX + bcol;
    float4 pb[4];
#define BPRE(ck) do { \
        const float* src = gx + (size_t)(ck) * 32 * NPIX; \
        pb[0] = *(const float4*)(src); \
        pb[1] = *(const float4*)(src + 4); \
        pb[2] = *(const float4*)(src + 8); \
        pb[3] = *(const float4*)(src + 12); \
    } while (0)
#define BSTORE(s) do { \
        uint32_t h[8]; \
        h[0] = pack_h2(pb[0].x, pb[0].y); h[1] = pack_h2(pb[0].z, pb[0].w); \
        h[2] = pack_h2(pb[1].x, pb[1].y); h[3] = pack_h2(pb[1].z, pb[1].w); \
        h[4] = pack_h2(pb[2].x, pb[2].y); h[5] = pack_h2(pb[2].z, pb[2].w); \
        h[6] = pack_h2(pb[3].x, pb[3].y); h[7] = pack_h2(pb[3].z, pb[3].w); \
        uint4* dst = (uint4*)(sm + S_B + (s) * BS_SIZE + (bkr * BS_PITCH + bns) * 2); \
        dst[0] = make_uint4(h[0], h[1], h[2], h[3]); \
        dst[1] = make_uint4(h[4], h[5], h[6], h[7]); \
    } while (0)

    float acc[2][8][4];
#pragma unroll
    for (int ms = 0; ms < 2; ms++)
#pragma unroll
        for (int ns = 0; ns < 8; ns++)
#pragma unroll
            for (int j = 0; j < 4; j++) acc[ms][ns][j] = 0.f;

    const int a_r = (lane & 7) + ((lane >> 3) & 1) * 8;
    const int a_c = (lane >> 4) * 8;
    const int b_r2 = (lane & 7) + ((lane >> 3) & 1) * 8;   // k offset (trans)
    const int b_c2 = (lane >> 4) * 8;                      // n offset (trans)

    BPRE(0);
    ISSUE_A(0, 0);
    ISSUE_A(1, 1);
    BSTORE(0);
    BPRE(1);

    for (int ck = 0; ck < 16; ck++) {
        const int sA = ck % 3, sB = ck & 1;
        if (ck < 15) CPWAIT1(); else CPWAIT0();
        __syncthreads();   // A stage sA ready; Bs[sB] stores visible; prev MMA done
        if (ck + 2 < 16) ISSUE_A(ck + 2, (ck + 2) % 3);
        if (ck + 1 < 16) BSTORE(sB ^ 1);
        if (ck + 2 < 16) BPRE(ck + 2);

        const uint32_t stA = sb + S_AH + sA * 10240;
        const uint32_t stB = sb + S_B + sB * BS_SIZE;
#pragma unroll
        for (int kk = 0; kk < 32; kk += 16) {
            uint32_t ah[2][4], bh[8][2];
#pragma unroll
            for (int ms = 0; ms < 2; ms++) {
                uint32_t row = warpM * 32 + ms * 16 + a_r;
                ldsm_x4(ah[ms], stA + (row * 40 + kk + a_c) * 2);
            }
#pragma unroll
            for (int np = 0; np < 4; np++) {
                uint32_t row = kk + b_r2;
                uint32_t col = warpN * 64 + np * 16 + b_c2;
                uint32_t r4[4];
                ldsm_x4_t(r4, stB + (row * BS_PITCH + col) * 2);
                bh[np * 2][0] = r4[0]; bh[np * 2][1] = r4[1];
                bh[np * 2 + 1][0] = r4[2]; bh[np * 2 + 1][1] = r4[3];
            }
#pragma unroll
            for (int ms = 0; ms < 2; ms++)
#pragma unroll
                for (int ns = 0; ns < 8; ns++)
                    mma16816(acc[ms][ns], ah[ms], bh[ns]);
        }
    }

    // writeback (predicated on n for the edge block)
    const int r_base = lane >> 2;
    const int c_base = (lane & 3) * 2;
#pragma unroll
    for (int ms = 0; ms < 2; ms++) {
#pragma unroll
        for (int ns = 0; ns < 8; ns++) {
            int m_loc = warpM * 32 + ms * 16 + r_base;
            int n_loc = warpN * 64 + ns * 8 + c_base;
            int m_g = bm * 128 + m_loc;
            int n_g = n0 + n_loc;
            if (n_g >= NPIX) continue;
            float* dst0;
            float* dst1;
            if (bm < 4) {
                dst0 = g_xv + ((size_t)bb * CXV + m_g) * NPIX + n_g;
                dst1 = g_xv + ((size_t)bb * CXV + m_g + 8) * NPIX + n_g;
            } else {
                dst0 = g_u + ((size_t)bb * CU + (m_g - 512)) * NPIX + n_g;
                dst1 = g_u + ((size_t)bb * CU + (m_g - 512 + 8)) * NPIX + n_g;
            }
            *(float2*)dst0 = make_float2(acc[ms][ns][0], acc[ms][ns][1]);
            *(float2*)dst1 = make_float2(acc[ms][ns][2], acc[ms][ns][3]);
        }
    }

    // fused GN partial stats (u rows only)
    if (bm >= 4) {
#pragma unroll
        for (int ms = 0; ms < 2; ms++) {
#pragma unroll
            for (int half = 0; half < 2; half++) {
                float s = 0.f, s2 = 0.f;
#pragma unroll
                for (int ns = 0; ns < 8; ns++) {
                    int n_loc = warpN * 64 + ns * 8 + c_base;
#pragma unroll
                    for (int j = 0; j < 2; j++) {
                        if (n0 + n_loc + j < NPIX) {
                            float v = acc[ms][ns][half * 2 + j];
                            s += v;
                            s2 += v * v;
                        }
                    }
                }
#pragma unroll
                for (int o = 16; o > 0; o >>= 1) {
                    s  += __shfl_xor_sync(0xffffffffu, s, o);
                    s2 += __shfl_xor_sync(0xffffffffu, s2, o);
                }
                if (lane == 0) {
                    red[wid][ms * 2 + half][0] = s;
                    red[wid][ms * 2 + half][1] = s2;
                }
            }
        }
    }
    __syncthreads();
    if (bm >= 4 && tid < 16) {
        int wM = tid >> 2, grp = tid & 3;
        float s  = red[wM * 2][grp][0] + red[wM * 2 + 1][grp][0];
        float s2 = red[wM * 2][grp][1] + red[wM * 2 + 1][grp][1];
        g_part2[bb][bm - 4][bx][tid][0] = s;
        g_part2[bb][bm - 4][bx][tid][1] = s2;
    }
}

// ---------------------------------------------------------------------------
// Kernel 2: epilogue (R14 winner: band-tiled, row-rolling, plane-major xs)
// ---------------------------------------------------------------------------
__global__ __launch_bounds__(256) void epi_kernel(const float* __restrict__ gn_gamma,
                                                  const float* __restrict__ gn_beta,
                                                  const float* __restrict__ w2,
                                                  const float* __restrict__ b2,
                                                  float* __restrict__ out) {
    extern __shared__ float dsm[];
    float4 (*xs4)[6][58] = (float4(*)[6][58])(dsm + E_XS);
    float (*th)[224]     = (float(*)[224])(dsm + E_TH);
    float* s_w2t         = dsm + E_W2T;    // [i][t] stride 40
    float* s_b2          = dsm + E_B2;
    float (*s_gn)[4]     = (float(*)[4])(dsm + E_GN);

    const int band = blockIdx.x;          // 0..13
    const int f = blockIdx.y;
    const int bb = blockIdx.z;
    const int y0 = band * 4;
    const int tid = threadIdx.x;

    for (int idx = tid; idx < 36 * 32; idx += 256) {
        int t = idx / 32, i = idx & 31;
        s_w2t[i * 40 + t] = w2[t * 32 + i];     // t = G*9 + tap
    }
    if (tid < 36) s_b2[tid] = b2[tid];
    if (tid >= 64 && tid < 96) {
        int i = tid - 64;
        int bmp = i >> 4, il = i & 15;
        float s = 0.f, s2 = 0.f;
        for (int bx = 0; bx < 25; bx++) {
            s  += g_part2[bb][bmp][bx][il][0];
            s2 += g_part2[bb][bmp][bx][il][1];
        }
        float mean = s / 25088.f;
        float var = s2 / 25088.f - mean * mean;
        s_gn[i][0] = mean;
        s_gn[i][1] = rsqrtf(var + 1e-5f);
        s_gn[i][2] = gn_gamma[i * 8 + f];
        s_gn[i][3] = gn_beta[i * 8 + f];
    }
    __syncthreads();

    // Phase A: per-pixel 36 thetas (coalesced u loads)
    if (tid < 224) {
        int p = y0 * HW + tid;
        float acc[36];
#pragma unroll
        for (int t = 0; t < 36; t++) acc[t] = s_b2[t];
        const float* __restrict__ ub = g_u + ((size_t)bb * CU + f) * NPIX + p;
#pragma unroll 4
        for (int i = 0; i < 32; i++) {
            float v = ub[(size_t)i * 8 * NPIX];
            v = (v - s_gn[i][0]) * s_gn[i][1] * s_gn[i][2] + s_gn[i][3];
            v = fmaxf(v, 0.f);
            const float4* wp = (const float4*)(s_w2t + i * 40);
#pragma unroll
            for (int q = 0; q < 9; q++) {
                float4 w4 = wp[q];
                acc[q * 4 + 0] = fmaf(w4.x, v, acc[q * 4 + 0]);
                acc[q * 4 + 1] = fmaf(w4.y, v, acc[q * 4 + 1]);
                acc[q * 4 + 2] = fmaf(w4.z, v, acc[q * 4 + 2]);
                acc[q * 4 + 3] = fmaf(w4.w, v, acc[q * 4 + 3]);
            }
        }
#pragma unroll
        for (int t = 0; t < 36; t++) th[t][tid] = acc[t];
    }

    int tap[9];
#pragma unroll
    for (int t = 0; t < 9; t++) tap[t] = c_tap[f][t];

    for (int G = 0; G < 4; G++) {
        __syncthreads();
        for (int pos = tid; pos < 6 * 58; pos += 256) {
            int yy = pos / 58, xx = pos - yy * 58;
            int gy = y0 - 1 + yy, gx = xx - 1;
            bool ok = (gy >= 0 && gy < HW && gx >= 0 && gx < HW);
            size_t base = ((size_t)bb * CXV + G * 128 + f) * NPIX + gy * HW + gx;
            float v[16];
#pragma unroll
            for (int c = 0; c < 16; c++)
                v[c] = ok ? g_xv[base + (size_t)c * 8 * NPIX] : 0.f;
#pragma unroll
            for (int q = 0; q < 4; q++)
                xs4[q][yy][xx] = make_float4(v[q * 4], v[q * 4 + 1],
                                             v[q * 4 + 2], v[q * 4 + 3]);
        }
        __syncthreads();

        if (tid < 224) {
            int cg = tid / 56, px = tid - cg * 56;
            float4 r0[3], r1[3], r2[3];
#pragma unroll
            for (int c = 0; c < 3; c++) {
                r0[c] = xs4[cg][0][px + c];
                r1[c] = xs4[cg][1][px + c];
                r2[c] = xs4[cg][2][px + c];
            }
            size_t obase0 = ((size_t)bb * CXV + G * 128 + f) * NPIX
                          + y0 * HW + px;
#pragma unroll
            for (int py = 0; py < 4; py++) {
                int pix = py * 56 + px;
                float a0 = 0.f, a1 = 0.f, a2 = 0.f, a3 = 0.f;
#pragma unroll
                for (int tj = 0; tj < 3; tj++) {
                    float w0 = th[G * 9 + tap[0 + tj]][pix];
                    float w1 = th[G * 9 + tap[3 + tj]][pix];
                    float w2v = th[G * 9 + tap[6 + tj]][pix];
                    float4 v0 = r0[tj], v1 = r1[tj], v2 = r2[tj];
                    a0 = fmaf(w0, v0.x, fmaf(w1, v1.x, fmaf(w2v, v2.x, a0)));
                    a1 = fmaf(w0, v0.y, fmaf(w1, v1.y, fmaf(w2v, v2.y, a1)));
                    a2 = fmaf(w0, v0.z, fmaf(w1, v1.z, fmaf(w2v, v2.z, a2)));
                    a3 = fmaf(w0, v0.w, fmaf(w1, v1.w, fmaf(w2v, v2.w, a3)));
                }
                size_t ob = obase0 + (size_t)(cg * 4) * 8 * NPIX + py * HW;
                out[ob] = a0;
                out[ob + (size_t)8 * NPIX] = a1;
                out[ob + (size_t)16 * NPIX] = a2;
                out[ob + (size_t)24 * NPIX] = a3;
                if (py < 3) {
#pragma unroll
                    for (int c = 0; c < 3; c++) {
                        r0[c] = r1[c];
                        r1[c] = r2[c];
                        r2[c] = xs4[cg][py + 3][px + c];
                    }
                }
            }
        }
    }
}

// ---------------------------------------------------------------------------
extern "C" void kernel_launch(void* const* d_in, const int* in_sizes, int n_in,
                              void* d_out, int out_size) {
    const float* x        = (const float*)d_in[0];
    const float* w_v      = (const float*)d_in[1];
    const float* w1       = (const float*)d_in[2];
    const float* gn_gamma = (const float*)d_in[3];
    const float* gn_beta  = (const float*)d_in[4];
    const float* w2       = (const float*)d_in[5];
    const float* b2       = (const float*)d_in[6];
    float* out = (float*)d_out;

    cudaFuncSetAttribute(gemm_mma_kernel,
                         cudaFuncAttributeMaxDynamicSharedMemorySize, S_TOTAL);
    cudaFuncSetAttribute(epi_kernel,
                         cudaFuncAttributeMaxDynamicSharedMemorySize, E_BYTES);

    expand_w_kernel<<<(MROWS * KIN + 255) / 256, 256>>>(w_v, w1);
    {
        dim3 grid(25, 6, BATCH);     // (n-tile128, m-tile128, batch)
        gemm_mma_kernel<<<grid, 256, S_TOTAL>>>(x);
    }
    {
        dim3 grid(14, 8, BATCH);     // (bands, f, b)
        epi_kernel<<<grid, 256, E_BYTES>>>(gn_gamma, gn_beta, w2, b2, out);
    }
}

// round 16
// speedup vs baseline: 1.0869x; 1.0869x over previous
#include <cuda_runtime.h>
#include <cuda_fp16.h>
#include <math.h>
#include <stdint.h>

// Problem constants
#define BATCH 8
#define HW 56
#define NPIX 3136
#define CMID 32
#define CXV 512             // cout*8
#define CU 256              // cmid*8
#define KIN 512             // GEMM K
#define MROWS 768           // 512 xv + 256 u

// ---- device scratch (no allocation allowed) ----
__device__ __half g_Wh[MROWS * KIN];                // [m][k] row-major fp16
__device__ __half g_xh[(size_t)BATCH * NPIX * KIN]; // [b][n][k] fp16
__device__ __half g_xv[(size_t)BATCH * CXV * NPIX]; // fp16 intermediate
__device__ __half g_u[(size_t)BATCH * CU * NPIX];   // fp16 intermediate
// GN partials written by GEMM: [b][bm-4][bx(25)][i_local(16)][{sum,sumsq}]
__device__ float g_part2[BATCH][2][25][16][2];

__constant__ int c_perm[8][8] = {
    {0, 1, 2, 3, 4, 5, 6, 7},
    {3, 0, 1, 2, 5, 6, 7, 4},
    {2, 3, 0, 1, 6, 7, 4, 5},
    {1, 2, 3, 0, 7, 4, 5, 6},
    {4, 5, 6, 7, 0, 1, 2, 3},
    {5, 6, 7, 4, 3, 0, 1, 2},
    {6, 7, 4, 5, 2, 3, 0, 1},
    {7, 4, 5, 6, 1, 2, 3, 0},
};
__constant__ int c_tap[8][9] = {
    {0,1,2,3,4,5,6,7,8},
    {2,5,8,1,4,7,0,3,6},
    {8,7,6,5,4,3,2,1,0},
    {6,3,0,7,4,1,8,5,2},
    {2,1,0,5,4,3,8,7,6},
    {8,5,2,7,4,1,6,3,0},
    {6,7,8,3,4,5,0,1,2},
    {0,3,6,1,4,7,2,5,8},
};

__device__ __forceinline__ uint32_t smem_u32(const void* p) {
    uint32_t a;
    asm("{ .reg .u64 t; cvta.to.shared.u64 t, %1; cvt.u32.u64 %0, t; }" : "=r"(a) : "l"(p));
    return a;
}
__device__ __forceinline__ void ldsm_x4(uint32_t* r, uint32_t addr) {
    asm volatile("ldmatrix.sync.aligned.m8n8.x4.shared.b16 {%0,%1,%2,%3}, [%4];"
                 : "=r"(r[0]), "=r"(r[1]), "=r"(r[2]), "=r"(r[3]) : "r"(addr));
}
__device__ __forceinline__ void mma16816(float* c, const uint32_t* a, const uint32_t* b) {
    asm volatile("mma.sync.aligned.m16n8k16.row.col.f32.f16.f16.f32 "
                 "{%0,%1,%2,%3}, {%4,%5,%6,%7}, {%8,%9}, {%0,%1,%2,%3};"
                 : "+f"(c[0]), "+f"(c[1]), "+f"(c[2]), "+f"(c[3])
                 : "r"(a[0]), "r"(a[1]), "r"(a[2]), "r"(a[3]), "r"(b[0]), "r"(b[1]));
}
#define CP16(dst, src) \
    asm volatile("cp.async.cg.shared.global [%0], [%1], 16;" :: "r"(dst), "l"(src))
#define CPCOMMIT() asm volatile("cp.async.commit_group;")
#define CPWAIT1() asm volatile("cp.async.wait_group 1;")
#define CPWAIT0() asm volatile("cp.async.wait_group 0;")

// gemm smem per stage: 128 rows x 80B (40 fp16, padded) for A and B
#define S_AH 0
#define S_BH 10240
#define S_STAGE 20480
#define S_TOTAL (3 * S_STAGE)   // 61440

// epi dynamic smem (float offsets); plane-major xs
#define E_XS 0                   // float4[4][6][58] = 5568 floats
#define E_TH 5568                // [36][224] = 8064
#define E_W2T 13632              // [32][40] = 1280
#define E_B2 14912               // [40]
#define E_GN 14952               // [32][4] = 128
#define E_FLOATS 15080
#define E_BYTES (E_FLOATS * 4)   // 60320

// ---------------------------------------------------------------------------
// Kernel 0: expand W -> fp16 [m][k] row-major
// ---------------------------------------------------------------------------
__global__ void expand_w_kernel(const float* __restrict__ w_v,
                                const float* __restrict__ w1) {
    int idx = blockIdx.x * 256 + threadIdx.x;
    if (idx >= MROWS * KIN) return;
    int m = idx >> 9, k = idx & 511;
    int i = k >> 3, f = k & 7;
    float val;
    if (m < 512) {
        int o = m >> 3, g = m & 7;
        val = w_v[(o * 64 + i) * 8 + c_perm[g][f]];
    } else {
        int m2 = m - 512;
        int o = m2 >> 3, g = m2 & 7;
        val = w1[(o * 64 + i) * 8 + c_perm[g][f]];
    }
    g_Wh[idx] = __float2half_rn(val);
}

// ---------------------------------------------------------------------------
// Kernel 0b: transpose x -> fp16 [b][n][k] row-major
// ---------------------------------------------------------------------------
__global__ __launch_bounds__(256) void convx_kernel(const float* __restrict__ x) {
    const int nt = blockIdx.x, ck = blockIdx.y, bb = blockIdx.z;
    __shared__ float s[64][65];
    const int tid = threadIdx.x;
    const float* __restrict__ src = x + ((size_t)bb * KIN + ck * 64) * NPIX + nt * 64;
#pragma unroll
    for (int i = 0; i < 16; i++) {
        int flat = i * 256 + tid;
        int kk = flat >> 6, nn = flat & 63;
        s[kk][nn] = src[(size_t)kk * NPIX + nn];
    }
    __syncthreads();
#pragma unroll
    for (int it = 0; it < 2; it++) {
        int task = it * 256 + tid;
        int nn = task >> 3, g = task & 7;
        int n = nt * 64 + nn;
        uint32_t hw[4];
#pragma unroll
        for (int j = 0; j < 4; j++) {
            __half h0 = __float2half_rn(s[g * 8 + 2 * j][nn]);
            __half h1 = __float2half_rn(s[g * 8 + 2 * j + 1][nn]);
            hw[j] = (uint32_t)__half_as_ushort(h0) | ((uint32_t)__half_as_ushort(h1) << 16);
        }
        size_t g4 = ((size_t)bb * NPIX + n) * 64 + ck * 8 + g;
        ((uint4*)g_xh)[g4] = make_uint4(hw[0], hw[1], hw[2], hw[3]);
    }
}

// ---------------------------------------------------------------------------
// Kernel 1: fp16 mma.sync GEMM + fused GN partial stats for u rows.
// tile 128M x 128N, 256 thr (8 warps 4Mx2N), BK=32, cp.async 3-stage.
// Writeback in fp16 (g_xv/g_u); GN stats from fp32 accumulators.
// ---------------------------------------------------------------------------
__global__ __launch_bounds__(256, 2) void gemm_mma_kernel() {
    extern __shared__ char sm[];
    __shared__ float red[8][4][2];   // [wid][ms*2+half][{s,s2}]
    const uint32_t sb = smem_u32(sm);
    const int tid = threadIdx.x;
    const int lane = tid & 31, wid = tid >> 5;
    const int warpM = wid >> 1, warpN = wid & 1;
    const int bx = blockIdx.x, bm = blockIdx.y, bb = blockIdx.z;
    const int n0 = bx * 128;

    const char* __restrict__ gAh = (const char*)g_Wh + (size_t)bm * 128 * 1024;
    const int ar = tid >> 1, ag = (tid & 1) * 32;
    int brow = n0 + ar;
    if (brow > NPIX - 1) brow = NPIX - 1;     // clamp for edge n-block
    const char* __restrict__ gBh = (const char*)g_xh + ((size_t)bb * NPIX + brow) * 1024;

#define ISSUE(ck, s) do { \
        uint32_t stb_ = sb + (s) * S_STAGE; \
        const char* a0 = gAh + (size_t)ar * 1024 + (ck) * 64 + ag; \
        uint32_t da0 = stb_ + S_AH + ar * 80 + ag; \
        CP16(da0, a0); CP16(da0 + 16, a0 + 16); \
        const char* b0 = gBh + (ck) * 64 + ag; \
        uint32_t db0 = stb_ + S_BH + ar * 80 + ag; \
        CP16(db0, b0); CP16(db0 + 16, b0 + 16); \
        CPCOMMIT(); \
    } while (0)

    float acc[2][8][4];
#pragma unroll
    for (int ms = 0; ms < 2; ms++)
#pragma unroll
        for (int ns = 0; ns < 8; ns++)
#pragma unroll
            for (int j = 0; j < 4; j++) acc[ms][ns][j] = 0.f;

    const int a_r = (lane & 7) + ((lane >> 3) & 1) * 8;
    const int a_c = (lane >> 4) * 8;
    const int b_r = (lane & 7) + ((lane >> 4) & 1) * 8;
    const int b_c = ((lane >> 3) & 1) * 8;

    ISSUE(0, 0);
    ISSUE(1, 1);

    for (int ck = 0; ck < 16; ck++) {
        const int s = ck % 3;
        if (ck < 15) CPWAIT1(); else CPWAIT0();
        __syncthreads();
        if (ck + 2 < 16) ISSUE(ck + 2, (ck + 2) % 3);

        const uint32_t stb = sb + s * S_STAGE;
#pragma unroll
        for (int kk = 0; kk < 32; kk += 16) {
            uint32_t ah[2][4], bh[8][2];
#pragma unroll
            for (int ms = 0; ms < 2; ms++) {
                uint32_t row = warpM * 32 + ms * 16 + a_r;
                ldsm_x4(ah[ms], stb + S_AH + (row * 40 + kk + a_c) * 2);
            }
#pragma unroll
            for (int np = 0; np < 4; np++) {
                uint32_t row = warpN * 64 + np * 16 + b_r;
                uint32_t r4[4];
                ldsm_x4(r4, stb + S_BH + (row * 40 + kk + b_c) * 2);
                bh[np * 2][0] = r4[0]; bh[np * 2][1] = r4[1];
                bh[np * 2 + 1][0] = r4[2]; bh[np * 2 + 1][1] = r4[3];
            }
#pragma unroll
            for (int ms = 0; ms < 2; ms++)
#pragma unroll
                for (int ns = 0; ns < 8; ns++)
                    mma16816(acc[ms][ns], ah[ms], bh[ns]);
        }
        __syncthreads();
    }

    // writeback fp16 (predicated on n for the edge block)
    const int r_base = lane >> 2;
    const int c_base = (lane & 3) * 2;
#pragma unroll
    for (int ms = 0; ms < 2; ms++) {
#pragma unroll
        for (int ns = 0; ns < 8; ns++) {
            int m_loc = warpM * 32 + ms * 16 + r_base;
            int n_loc = warpN * 64 + ns * 8 + c_base;
            int m_g = bm * 128 + m_loc;
            int n_g = n0 + n_loc;
            if (n_g >= NPIX) continue;
            __half2 v0 = __floats2half2_rn(acc[ms][ns][0], acc[ms][ns][1]);
            __half2 v1 = __floats2half2_rn(acc[ms][ns][2], acc[ms][ns][3]);
            if (bm < 4) {
                *(__half2*)&g_xv[((size_t)bb * CXV + m_g) * NPIX + n_g] = v0;
                *(__half2*)&g_xv[((size_t)bb * CXV + m_g + 8) * NPIX + n_g] = v1;
            } else {
                *(__half2*)&g_u[((size_t)bb * CU + (m_g - 512)) * NPIX + n_g] = v0;
                *(__half2*)&g_u[((size_t)bb * CU + (m_g - 512 + 8)) * NPIX + n_g] = v1;
            }
        }
    }

    // fused GN partial stats from fp32 accumulators (u rows only)
    if (bm >= 4) {
#pragma unroll
        for (int ms = 0; ms < 2; ms++) {
#pragma unroll
            for (int half = 0; half < 2; half++) {
                float s = 0.f, s2 = 0.f;
#pragma unroll
                for (int ns = 0; ns < 8; ns++) {
                    int n_loc = warpN * 64 + ns * 8 + c_base;
#pragma unroll
                    for (int j = 0; j < 2; j++) {
                        if (n0 + n_loc + j < NPIX) {
                            float v = acc[ms][ns][half * 2 + j];
                            s += v;
                            s2 += v * v;
                        }
                    }
                }
#pragma unroll
                for (int o = 16; o > 0; o >>= 1) {
                    s  += __shfl_xor_sync(0xffffffffu, s, o);
                    s2 += __shfl_xor_sync(0xffffffffu, s2, o);
                }
                if (lane == 0) {
                    red[wid][ms * 2 + half][0] = s;
                    red[wid][ms * 2 + half][1] = s2;
                }
            }
        }
    }
    __syncthreads();
    if (bm >= 4 && tid < 16) {
        int wM = tid >> 2, grp = tid & 3;
        float s  = red[wM * 2][grp][0] + red[wM * 2 + 1][grp][0];
        float s2 = red[wM * 2][grp][1] + red[wM * 2 + 1][grp][1];
        g_part2[bb][bm - 4][bx][tid][0] = s;
        g_part2[bb][bm - 4][bx][tid][1] = s2;
    }
}

// ---------------------------------------------------------------------------
// Kernel 2: epilogue (R14 structure; fp16 g_u/g_xv reads)
// ---------------------------------------------------------------------------
__global__ __launch_bounds__(256) void epi_kernel(const float* __restrict__ gn_gamma,
                                                  const float* __restrict__ gn_beta,
                                                  const float* __restrict__ w2,
                                                  const float* __restrict__ b2,
                                                  float* __restrict__ out) {
    extern __shared__ float dsm[];
    float4 (*xs4)[6][58] = (float4(*)[6][58])(dsm + E_XS);
    float (*th)[224]     = (float(*)[224])(dsm + E_TH);
    float* s_w2t         = dsm + E_W2T;    // [i][t] stride 40
    float* s_b2          = dsm + E_B2;
    float (*s_gn)[4]     = (float(*)[4])(dsm + E_GN);

    const int band = blockIdx.x;          // 0..13
    const int f = blockIdx.y;
    const int bb = blockIdx.z;
    const int y0 = band * 4;
    const int tid = threadIdx.x;

    for (int idx = tid; idx < 36 * 32; idx += 256) {
        int t = idx / 32, i = idx & 31;
        s_w2t[i * 40 + t] = w2[t * 32 + i];     // t = G*9 + tap
    }
    if (tid < 36) s_b2[tid] = b2[tid];
    if (tid >= 64 && tid < 96) {
        int i = tid - 64;
        int bmp = i >> 4, il = i & 15;
        float s = 0.f, s2 = 0.f;
        for (int bx = 0; bx < 25; bx++) {
            s  += g_part2[bb][bmp][bx][il][0];
            s2 += g_part2[bb][bmp][bx][il][1];
        }
        float mean = s / 25088.f;
        float var = s2 / 25088.f - mean * mean;
        s_gn[i][0] = mean;
        s_gn[i][1] = rsqrtf(var + 1e-5f);
        s_gn[i][2] = gn_gamma[i * 8 + f];
        s_gn[i][3] = gn_beta[i * 8 + f];
    }
    __syncthreads();

    // Phase A: per-pixel 36 thetas (coalesced fp16 u loads)
    if (tid < 224) {
        int p = y0 * HW + tid;
        float acc[36];
#pragma unroll
        for (int t = 0; t < 36; t++) acc[t] = s_b2[t];
        const __half* __restrict__ ub = g_u + ((size_t)bb * CU + f) * NPIX + p;
#pragma unroll 4
        for (int i = 0; i < 32; i++) {
            float v = __half2float(ub[(size_t)i * 8 * NPIX]);
            v = (v - s_gn[i][0]) * s_gn[i][1] * s_gn[i][2] + s_gn[i][3];
            v = fmaxf(v, 0.f);
            const float4* wp = (const float4*)(s_w2t + i * 40);
#pragma unroll
            for (int q = 0; q < 9; q++) {
                float4 w4 = wp[q];
                acc[q * 4 + 0] = fmaf(w4.x, v, acc[q * 4 + 0]);
                acc[q * 4 + 1] = fmaf(w4.y, v, acc[q * 4 + 1]);
                acc[q * 4 + 2] = fmaf(w4.z, v, acc[q * 4 + 2]);
                acc[q * 4 + 3] = fmaf(w4.w, v, acc[q * 4 + 3]);
            }
        }
#pragma unroll
        for (int t = 0; t < 36; t++) th[t][tid] = acc[t];
    }

    int tap[9];
#pragma unroll
    for (int t = 0; t < 9; t++) tap[t] = c_tap[f][t];

    for (int G = 0; G < 4; G++) {
        __syncthreads();
        for (int pos = tid; pos < 6 * 58; pos += 256) {
            int yy = pos / 58, xx = pos - yy * 58;
            int gy = y0 - 1 + yy, gx = xx - 1;
            bool ok = (gy >= 0 && gy < HW && gx >= 0 && gx < HW);
            size_t base = ((size_t)bb * CXV + G * 128 + f) * NPIX + gy * HW + gx;
            float v[16];
#pragma unroll
            for (int c = 0; c < 16; c++)
                v[c] = ok ? __half2float(g_xv[base + (size_t)c * 8 * NPIX]) : 0.f;
#pragma unroll
            for (int q = 0; q < 4; q++)
                xs4[q][yy][xx] = make_float4(v[q * 4], v[q * 4 + 1],
                                             v[q * 4 + 2], v[q * 4 + 3]);
        }
        __syncthreads();

        if (tid < 224) {
            int cg = tid / 56, px = tid - cg * 56;
            float4 r0[3], r1[3], r2[3];
#pragma unroll
            for (int c = 0; c < 3; c++) {
                r0[c] = xs4[cg][0][px + c];
                r1[c] = xs4[cg][1][px + c];
                r2[c] = xs4[cg][2][px + c];
            }
            size_t obase0 = ((size_t)bb * CXV + G * 128 + f) * NPIX
                          + y0 * HW + px;
#pragma unroll
            for (int py = 0; py < 4; py++) {
                int pix = py * 56 + px;
                float a0 = 0.f, a1 = 0.f, a2 = 0.f, a3 = 0.f;
#pragma unroll
                for (int tj = 0; tj < 3; tj++) {
                    float w0 = th[G * 9 + tap[0 + tj]][pix];
                    float w1 = th[G * 9 + tap[3 + tj]][pix];
                    float w2v = th[G * 9 + tap[6 + tj]][pix];
                    float4 v0 = r0[tj], v1 = r1[tj], v2 = r2[tj];
                    a0 = fmaf(w0, v0.x, fmaf(w1, v1.x, fmaf(w2v, v2.x, a0)));
                    a1 = fmaf(w0, v0.y, fmaf(w1, v1.y, fmaf(w2v, v2.y, a1)));
                    a2 = fmaf(w0, v0.z, fmaf(w1, v1.z, fmaf(w2v, v2.z, a2)));
                    a3 = fmaf(w0, v0.w, fmaf(w1, v1.w, fmaf(w2v, v2.w, a3)));
                }
                size_t ob = obase0 + (size_t)(cg * 4) * 8 * NPIX + py * HW;
                out[ob] = a0;
                out[ob + (size_t)8 * NPIX] = a1;
                out[ob + (size_t)16 * NPIX] = a2;
                out[ob + (size_t)24 * NPIX] = a3;
                if (py < 3) {
#pragma unroll
                    for (int c = 0; c < 3; c++) {
                        r0[c] = r1[c];
                        r1[c] = r2[c];
                        r2[c] = xs4[cg][py + 3][px + c];
                    }
                }
            }
        }
    }
}

// ---------------------------------------------------------------------------
extern "C" void kernel_launch(void* const* d_in, const int* in_sizes, int n_in,
                              void* d_out, int out_size) {
    const float* x        = (const float*)d_in[0];
    const float* w_v      = (const float*)d_in[1];
    const float* w1       = (const float*)d_in[2];
    const float* gn_gamma = (const float*)d_in[3];
    const float* gn_beta  = (const float*)d_in[4];
    const float* w2       = (const float*)d_in[5];
    const float* b2       = (const float*)d_in[6];
    float* out = (float*)d_out;

    cudaFuncSetAttribute(gemm_mma_kernel,
                         cudaFuncAttributeMaxDynamicSharedMemorySize, S_TOTAL);
    cudaFuncSetAttribute(epi_kernel,
                         cudaFuncAttributeMaxDynamicSharedMemorySize, E_BYTES);

    expand_w_kernel<<<(MROWS * KIN + 255) / 256, 256>>>(w_v, w1);
    {
        dim3 grid(49, 8, BATCH);
        convx_kernel<<<grid, 256>>>(x);
    }
    {
        dim3 grid(25, 6, BATCH);     // (n-tile128, m-tile128, batch)
        gemm_mma_kernel<<<grid, 256, S_TOTAL>>>();
    }
    {
        dim3 grid(14, 8, BATCH);     // (bands, f, b)
        epi_kernel<<<grid, 256, E_BYTES>>>(gn_gamma, gn_beta, w2, b2, out);
    }
}

// round 17
// speedup vs baseline: 1.1249x; 1.0350x over previous
#include <cuda_runtime.h>
#include <cuda_fp16.h>
#include <math.h>
#include <stdint.h>

// Problem constants
#define BATCH 8
#define HW 56
#define NPIX 3136
#define CMID 32
#define CXV 512             // cout*8
#define CU 256              // cmid*8
#define KIN 512             // GEMM K
#define MROWS 768           // 512 xv + 256 u

// ---- device scratch (no allocation allowed) ----
__device__ __half g_Wh[MROWS * KIN];                // [m][k] row-major fp16
__device__ __half g_xh[(size_t)BATCH * NPIX * KIN]; // [b][n][k] fp16
__device__ __half g_xv[(size_t)BATCH * CXV * NPIX]; // fp16 intermediate
__device__ __half g_u[(size_t)BATCH * CU * NPIX];   // fp16 intermediate
// GN partials written by GEMM: [b][bm-4][bx(25)][i_local(16)][{sum,sumsq}]
__device__ float g_part2[BATCH][2][25][16][2];

__constant__ int c_perm[8][8] = {
    {0, 1, 2, 3, 4, 5, 6, 7},
    {3, 0, 1, 2, 5, 6, 7, 4},
    {2, 3, 0, 1, 6, 7, 4, 5},
    {1, 2, 3, 0, 7, 4, 5, 6},
    {4, 5, 6, 7, 0, 1, 2, 3},
    {5, 6, 7, 4, 3, 0, 1, 2},
    {6, 7, 4, 5, 2, 3, 0, 1},
    {7, 4, 5, 6, 1, 2, 3, 0},
};
__constant__ int c_tap[8][9] = {
    {0,1,2,3,4,5,6,7,8},
    {2,5,8,1,4,7,0,3,6},
    {8,7,6,5,4,3,2,1,0},
    {6,3,0,7,4,1,8,5,2},
    {2,1,0,5,4,3,8,7,6},
    {8,5,2,7,4,1,6,3,0},
    {6,7,8,3,4,5,0,1,2},
    {0,3,6,1,4,7,2,5,8},
};

__device__ __forceinline__ uint32_t smem_u32(const void* p) {
    uint32_t a;
    asm("{ .reg .u64 t; cvta.to.shared.u64 t, %1; cvt.u32.u64 %0, t; }" : "=r"(a) : "l"(p));
    return a;
}
__device__ __forceinline__ void ldsm_x4(uint32_t* r, uint32_t addr) {
    asm volatile("ldmatrix.sync.aligned.m8n8.x4.shared.b16 {%0,%1,%2,%3}, [%4];"
                 : "=r"(r[0]), "=r"(r[1]), "=r"(r[2]), "=r"(r[3]) : "r"(addr));
}
__device__ __forceinline__ void ldsm_x4_t(uint32_t* r, uint32_t addr) {
    asm volatile("ldmatrix.sync.aligned.m8n8.x4.trans.shared.b16 {%0,%1,%2,%3}, [%4];"
                 : "=r"(r[0]), "=r"(r[1]), "=r"(r[2]), "=r"(r[3]) : "r"(addr));
}
__device__ __forceinline__ void mma16816(float* c, const uint32_t* a, const uint32_t* b) {
    asm volatile("mma.sync.aligned.m16n8k16.row.col.f32.f16.f16.f32 "
                 "{%0,%1,%2,%3}, {%4,%5,%6,%7}, {%8,%9}, {%0,%1,%2,%3};"
                 : "+f"(c[0]), "+f"(c[1]), "+f"(c[2]), "+f"(c[3])
                 : "r"(a[0]), "r"(a[1]), "r"(a[2]), "r"(a[3]), "r"(b[0]), "r"(b[1]));
}
#define CP16(dst, src) \
    asm volatile("cp.async.cg.shared.global [%0], [%1], 16;" :: "r"(dst), "l"(src))
#define CPCOMMIT() asm volatile("cp.async.commit_group;")
#define CPWAIT1() asm volatile("cp.async.wait_group 1;")
#define CPWAIT0() asm volatile("cp.async.wait_group 0;")

// gemm smem per stage: 128 rows x 80B (40 fp16, padded) for A and B
#define S_AH 0
#define S_BH 10240
#define S_STAGE 20480
#define S_TOTAL (3 * S_STAGE)   // 61440

// epi dynamic smem (byte offsets)
// union region: xs4 float4[4][6][58] = 22272 B  OR  V half[32][232] = 14848 B
#define EV_UNION 0
#define EV_TH    22272           // half[48][232] = 22272 B
#define EV_W2P   44544           // half[48][40]  = 3840 B (pitch 40, GEMM-A proven)
#define EV_B2P   48384           // float[48] = 192 B
#define EV_GN    48576           // float[32][4] = 512 B
#define E_BYTES  49088

// ---------------------------------------------------------------------------
// Kernel 0: expand W -> fp16 [m][k] row-major
// ---------------------------------------------------------------------------
__global__ void expand_w_kernel(const float* __restrict__ w_v,
                                const float* __restrict__ w1) {
    int idx = blockIdx.x * 256 + threadIdx.x;
    if (idx >= MROWS * KIN) return;
    int m = idx >> 9, k = idx & 511;
    int i = k >> 3, f = k & 7;
    float val;
    if (m < 512) {
        int o = m >> 3, g = m & 7;
        val = w_v[(o * 64 + i) * 8 + c_perm[g][f]];
    } else {
        int m2 = m - 512;
        int o = m2 >> 3, g = m2 & 7;
        val = w1[(o * 64 + i) * 8 + c_perm[g][f]];
    }
    g_Wh[idx] = __float2half_rn(val);
}

// ---------------------------------------------------------------------------
// Kernel 0b: transpose x -> fp16 [b][n][k] row-major
// ---------------------------------------------------------------------------
__global__ __launch_bounds__(256) void convx_kernel(const float* __restrict__ x) {
    const int nt = blockIdx.x, ck = blockIdx.y, bb = blockIdx.z;
    __shared__ float s[64][65];
    const int tid = threadIdx.x;
    const float* __restrict__ src = x + ((size_t)bb * KIN + ck * 64) * NPIX + nt * 64;
#pragma unroll
    for (int i = 0; i < 16; i++) {
        int flat = i * 256 + tid;
        int kk = flat >> 6, nn = flat & 63;
        s[kk][nn] = src[(size_t)kk * NPIX + nn];
    }
    __syncthreads();
#pragma unroll
    for (int it = 0; it < 2; it++) {
        int task = it * 256 + tid;
        int nn = task >> 3, g = task & 7;
        int n = nt * 64 + nn;
        uint32_t hw[4];
#pragma unroll
        for (int j = 0; j < 4; j++) {
            __half h0 = __float2half_rn(s[g * 8 + 2 * j][nn]);
            __half h1 = __float2half_rn(s[g * 8 + 2 * j + 1][nn]);
            hw[j] = (uint32_t)__half_as_ushort(h0) | ((uint32_t)__half_as_ushort(h1) << 16);
        }
        size_t g4 = ((size_t)bb * NPIX + n) * 64 + ck * 8 + g;
        ((uint4*)g_xh)[g4] = make_uint4(hw[0], hw[1], hw[2], hw[3]);
    }
}

// ---------------------------------------------------------------------------
// Kernel 1: fp16 mma.sync GEMM + fused GN partial stats for u rows.
// (unchanged from R16 winner)
// ---------------------------------------------------------------------------
__global__ __launch_bounds__(256, 2) void gemm_mma_kernel() {
    extern __shared__ char sm[];
    __shared__ float red[8][4][2];
    const uint32_t sb = smem_u32(sm);
    const int tid = threadIdx.x;
    const int lane = tid & 31, wid = tid >> 5;
    const int warpM = wid >> 1, warpN = wid & 1;
    const int bx = blockIdx.x, bm = blockIdx.y, bb = blockIdx.z;
    const int n0 = bx * 128;

    const char* __restrict__ gAh = (const char*)g_Wh + (size_t)bm * 128 * 1024;
    const int ar = tid >> 1, ag = (tid & 1) * 32;
    int brow = n0 + ar;
    if (brow > NPIX - 1) brow = NPIX - 1;
    const char* __restrict__ gBh = (const char*)g_xh + ((size_t)bb * NPIX + brow) * 1024;

#define ISSUE(ck, s) do { \
        uint32_t stb_ = sb + (s) * S_STAGE; \
        const char* a0 = gAh + (size_t)ar * 1024 + (ck) * 64 + ag; \
        uint32_t da0 = stb_ + S_AH + ar * 80 + ag; \
        CP16(da0, a0); CP16(da0 + 16, a0 + 16); \
        const char* b0 = gBh + (ck) * 64 + ag; \
        uint32_t db0 = stb_ + S_BH + ar * 80 + ag; \
        CP16(db0, b0); CP16(db0 + 16, b0 + 16); \
        CPCOMMIT(); \
    } while (0)

    float acc[2][8][4];
#pragma unroll
    for (int ms = 0; ms < 2; ms++)
#pragma unroll
        for (int ns = 0; ns < 8; ns++)
#pragma unroll
            for (int j = 0; j < 4; j++) acc[ms][ns][j] = 0.f;

    const int a_r = (lane & 7) + ((lane >> 3) & 1) * 8;
    const int a_c = (lane >> 4) * 8;
    const int b_r = (lane & 7) + ((lane >> 4) & 1) * 8;
    const int b_c = ((lane >> 3) & 1) * 8;

    ISSUE(0, 0);
    ISSUE(1, 1);

    for (int ck = 0; ck < 16; ck++) {
        const int s = ck % 3;
        if (ck < 15) CPWAIT1(); else CPWAIT0();
        __syncthreads();
        if (ck + 2 < 16) ISSUE(ck + 2, (ck + 2) % 3);

        const uint32_t stb = sb + s * S_STAGE;
#pragma unroll
        for (int kk = 0; kk < 32; kk += 16) {
            uint32_t ah[2][4], bh[8][2];
#pragma unroll
            for (int ms = 0; ms < 2; ms++) {
                uint32_t row = warpM * 32 + ms * 16 + a_r;
                ldsm_x4(ah[ms], stb + S_AH + (row * 40 + kk + a_c) * 2);
            }
#pragma unroll
            for (int np = 0; np < 4; np++) {
                uint32_t row = warpN * 64 + np * 16 + b_r;
                uint32_t r4[4];
                ldsm_x4(r4, stb + S_BH + (row * 40 + kk + b_c) * 2);
                bh[np * 2][0] = r4[0]; bh[np * 2][1] = r4[1];
                bh[np * 2 + 1][0] = r4[2]; bh[np * 2 + 1][1] = r4[3];
            }
#pragma unroll
            for (int ms = 0; ms < 2; ms++)
#pragma unroll
                for (int ns = 0; ns < 8; ns++)
                    mma16816(acc[ms][ns], ah[ms], bh[ns]);
        }
        __syncthreads();
    }

    const int r_base = lane >> 2;
    const int c_base = (lane & 3) * 2;
#pragma unroll
    for (int ms = 0; ms < 2; ms++) {
#pragma unroll
        for (int ns = 0; ns < 8; ns++) {
            int m_loc = warpM * 32 + ms * 16 + r_base;
            int n_loc = warpN * 64 + ns * 8 + c_base;
            int m_g = bm * 128 + m_loc;
            int n_g = n0 + n_loc;
            if (n_g >= NPIX) continue;
            __half2 v0 = __floats2half2_rn(acc[ms][ns][0], acc[ms][ns][1]);
            __half2 v1 = __floats2half2_rn(acc[ms][ns][2], acc[ms][ns][3]);
            if (bm < 4) {
                *(__half2*)&g_xv[((size_t)bb * CXV + m_g) * NPIX + n_g] = v0;
                *(__half2*)&g_xv[((size_t)bb * CXV + m_g + 8) * NPIX + n_g] = v1;
            } else {
                *(__half2*)&g_u[((size_t)bb * CU + (m_g - 512)) * NPIX + n_g] = v0;
                *(__half2*)&g_u[((size_t)bb * CU + (m_g - 512 + 8)) * NPIX + n_g] = v1;
            }
        }
    }

    if (bm >= 4) {
#pragma unroll
        for (int ms = 0; ms < 2; ms++) {
#pragma unroll
            for (int half = 0; half < 2; half++) {
                float s = 0.f, s2 = 0.f;
#pragma unroll
                for (int ns = 0; ns < 8; ns++) {
                    int n_loc = warpN * 64 + ns * 8 + c_base;
#pragma unroll
                    for (int j = 0; j < 2; j++) {
                        if (n0 + n_loc + j < NPIX) {
                            float v = acc[ms][ns][half * 2 + j];
                            s += v;
                            s2 += v * v;
                        }
                    }
                }
#pragma unroll
                for (int o = 16; o > 0; o >>= 1) {
                    s  += __shfl_xor_sync(0xffffffffu, s, o);
                    s2 += __shfl_xor_sync(0xffffffffu, s2, o);
                }
                if (lane == 0) {
                    red[wid][ms * 2 + half][0] = s;
                    red[wid][ms * 2 + half][1] = s2;
                }
            }
        }
    }
    __syncthreads();
    if (bm >= 4 && tid < 16) {
        int wM = tid >> 2, grp = tid & 3;
        float s  = red[wM * 2][grp][0] + red[wM * 2 + 1][grp][0];
        float s2 = red[wM * 2][grp][1] + red[wM * 2 + 1][grp][1];
        g_part2[bb][bm - 4][bx][tid][0] = s;
        g_part2[bb][bm - 4][bx][tid][1] = s2;
    }
}

// ---------------------------------------------------------------------------
// Kernel 2: epilogue. Phase A = tensor-core matvec th[48][224] =
// W2p[48][32] @ V[32][224] (V = relu(GN(u)) fp16). Phase B unchanged.
// ---------------------------------------------------------------------------
__global__ __launch_bounds__(256) void epi_kernel(const float* __restrict__ gn_gamma,
                                                  const float* __restrict__ gn_beta,
                                                  const float* __restrict__ w2,
                                                  const float* __restrict__ b2,
                                                  float* __restrict__ out) {
    extern __shared__ char esm[];
    float4 (*xs4)[6][58] = (float4(*)[6][58])(esm + EV_UNION);
    __half* Vh           = (__half*)(esm + EV_UNION);        // union w/ xs4
    __half* thh          = (__half*)(esm + EV_TH);           // [48][232]
    __half* w2p          = (__half*)(esm + EV_W2P);          // [48][40]
    float* s_b2p         = (float*)(esm + EV_B2P);           // [48]
    float (*s_gn)[4]     = (float(*)[4])(esm + EV_GN);

    const uint32_t sbV = smem_u32(esm) + EV_UNION;
    const uint32_t sbW = smem_u32(esm) + EV_W2P;

    const int band = blockIdx.x;          // 0..13
    const int f = blockIdx.y;
    const int bb = blockIdx.z;
    const int y0 = band * 4;
    const int tid = threadIdx.x;
    const int lane = tid & 31, wid = tid >> 5;

    // stage w2p [48][40] fp16 (pad rows/cols zero), b2p, s_gn
    for (int idx = tid; idx < 48 * 40; idx += 256) {
        int t = idx / 40, i = idx - t * 40;
        float v = (t < 36 && i < 32) ? w2[t * 32 + i] : 0.f;
        w2p[idx] = __float2half_rn(v);
    }
    if (tid < 48) s_b2p[tid] = (tid < 36) ? b2[tid] : 0.f;
    if (tid >= 64 && tid < 96) {
        int i = tid - 64;
        int bmp = i >> 4, il = i & 15;
        float s = 0.f, s2 = 0.f;
        for (int bx = 0; bx < 25; bx++) {
            s  += g_part2[bb][bmp][bx][il][0];
            s2 += g_part2[bb][bmp][bx][il][1];
        }
        float mean = s / 25088.f;
        float var = s2 / 25088.f - mean * mean;
        s_gn[i][0] = mean;
        s_gn[i][1] = rsqrtf(var + 1e-5f);
        s_gn[i][2] = gn_gamma[i * 8 + f];
        s_gn[i][3] = gn_beta[i * 8 + f];
    }
    __syncthreads();

    // build V[32][224] = relu(GN(u)), fp16, pitch 232
    if (tid < 224) {
        int p = y0 * HW + tid;
        const __half* __restrict__ ub = g_u + ((size_t)bb * CU + f) * NPIX + p;
#pragma unroll 4
        for (int i = 0; i < 32; i++) {
            float v = __half2float(ub[(size_t)i * 8 * NPIX]);
            v = (v - s_gn[i][0]) * s_gn[i][1] * s_gn[i][2] + s_gn[i][3];
            v = fmaxf(v, 0.f);
            Vh[i * 232 + tid] = __float2half_rn(v);
        }
    }
    __syncthreads();

    // MMA: warps 0..6 each own a 32-wide n-slice
    if (wid < 7) {
        const int n0 = wid * 32;
        const int a_r = (lane & 7) + ((lane >> 3) & 1) * 8;
        const int a_c = (lane >> 4) * 8;
        const int b_r2 = (lane & 7) + ((lane >> 3) & 1) * 8;   // k (trans)
        const int b_c2 = (lane >> 4) * 8;                      // n (trans)
        uint32_t afr[3][2][4];
#pragma unroll
        for (int mt = 0; mt < 3; mt++)
#pragma unroll
            for (int kc = 0; kc < 2; kc++)
                ldsm_x4(afr[mt][kc], sbW + ((mt * 16 + a_r) * 40 + kc * 16 + a_c) * 2);
        uint32_t bfr[2][4][2];
#pragma unroll
        for (int kc = 0; kc < 2; kc++)
#pragma unroll
            for (int nt = 0; nt < 2; nt++) {
                uint32_t r4[4];
                ldsm_x4_t(r4, sbV + ((kc * 16 + b_r2) * 232 + n0 + nt * 16 + b_c2) * 2);
                bfr[kc][nt * 2][0] = r4[0]; bfr[kc][nt * 2][1] = r4[1];
                bfr[kc][nt * 2 + 1][0] = r4[2]; bfr[kc][nt * 2 + 1][1] = r4[3];
            }
        const int rb = lane >> 2, cb = (lane & 3) * 2;
#pragma unroll
        for (int mt = 0; mt < 3; mt++) {
#pragma unroll
            for (int n8 = 0; n8 < 4; n8++) {
                float acc[4];
                acc[0] = acc[1] = s_b2p[mt * 16 + rb];
                acc[2] = acc[3] = s_b2p[mt * 16 + 8 + rb];
                mma16816(acc, afr[mt][0], bfr[0][n8]);
                mma16816(acc, afr[mt][1], bfr[1][n8]);
                int col = n0 + n8 * 8 + cb;
                *(__half2*)&thh[(mt * 16 + rb) * 232 + col] =
                    __floats2half2_rn(acc[0], acc[1]);
                *(__half2*)&thh[(mt * 16 + 8 + rb) * 232 + col] =
                    __floats2half2_rn(acc[2], acc[3]);
            }
        }
    }

    int tap[9];
#pragma unroll
    for (int t = 0; t < 9; t++) tap[t] = c_tap[f][t];

    for (int G = 0; G < 4; G++) {
        __syncthreads();   // th ready / V no longer needed (G=0); prev B done (G>0)
        for (int pos = tid; pos < 6 * 58; pos += 256) {
            int yy = pos / 58, xx = pos - yy * 58;
            int gy = y0 - 1 + yy, gx = xx - 1;
            bool ok = (gy >= 0 && gy < HW && gx >= 0 && gx < HW);
            size_t base = ((size_t)bb * CXV + G * 128 + f) * NPIX + gy * HW + gx;
            float v[16];
#pragma unroll
            for (int c = 0; c < 16; c++)
                v[c] = ok ? __half2float(g_xv[base + (size_t)c * 8 * NPIX]) : 0.f;
#pragma unroll
            for (int q = 0; q < 4; q++)
                xs4[q][yy][xx] = make_float4(v[q * 4], v[q * 4 + 1],
                                             v[q * 4 + 2], v[q * 4 + 3]);
        }
        __syncthreads();

        if (tid < 224) {
            int cg = tid / 56, px = tid - cg * 56;
            float4 r0[3], r1[3], r2[3];
#pragma unroll
            for (int c = 0; c < 3; c++) {
                r0[c] = xs4[cg][0][px + c];
                r1[c] = xs4[cg][1][px + c];
                r2[c] = xs4[cg][2][px + c];
            }
            size_t obase0 = ((size_t)bb * CXV + G * 128 + f) * NPIX
                          + y0 * HW + px;
#pragma unroll
            for (int py = 0; py < 4; py++) {
                int pix = py * 56 + px;
                float a0 = 0.f, a1 = 0.f, a2 = 0.f, a3 = 0.f;
#pragma unroll
                for (int tj = 0; tj < 3; tj++) {
                    float w0 = __half2float(thh[(G * 9 + tap[0 + tj]) * 232 + pix]);
                    float w1 = __half2float(thh[(G * 9 + tap[3 + tj]) * 232 + pix]);
                    float w2v = __half2float(thh[(G * 9 + tap[6 + tj]) * 232 + pix]);
                    float4 v0 = r0[tj], v1 = r1[tj], v2 = r2[tj];
                    a0 = fmaf(w0, v0.x, fmaf(w1, v1.x, fmaf(w2v, v2.x, a0)));
                    a1 = fmaf(w0, v0.y, fmaf(w1, v1.y, fmaf(w2v, v2.y, a1)));
                    a2 = fmaf(w0, v0.z, fmaf(w1, v1.z, fmaf(w2v, v2.z, a2)));
                    a3 = fmaf(w0, v0.w, fmaf(w1, v1.w, fmaf(w2v, v2.w, a3)));
                }
                size_t ob = obase0 + (size_t)(cg * 4) * 8 * NPIX + py * HW;
                out[ob] = a0;
                out[ob + (size_t)8 * NPIX] = a1;
                out[ob + (size_t)16 * NPIX] = a2;
                out[ob + (size_t)24 * NPIX] = a3;
                if (py < 3) {
#pragma unroll
                    for (int c = 0; c < 3; c++) {
                        r0[c] = r1[c];
                        r1[c] = r2[c];
                        r2[c] = xs4[cg][py + 3][px + c];
                    }
                }
            }
        }
    }
}

// ---------------------------------------------------------------------------
extern "C" void kernel_launch(void* const* d_in, const int* in_sizes, int n_in,
                              void* d_out, int out_size) {
    const float* x        = (const float*)d_in[0];
    const float* w_v      = (const float*)d_in[1];
    const float* w1       = (const float*)d_in[2];
    const float* gn_gamma = (const float*)d_in[3];
    const float* gn_beta  = (const float*)d_in[4];
    const float* w2       = (const float*)d_in[5];
    const float* b2       = (const float*)d_in[6];
    float* out = (float*)d_out;

    cudaFuncSetAttribute(gemm_mma_kernel,
                         cudaFuncAttributeMaxDynamicSharedMemorySize, S_TOTAL);
    cudaFuncSetAttribute(epi_kernel,
                         cudaFuncAttributeMaxDynamicSharedMemorySize, E_BYTES);

    expand_w_kernel<<<(MROWS * KIN + 255) / 256, 256>>>(w_v, w1);
    {
        dim3 grid(49, 8, BATCH);
        convx_kernel<<<grid, 256>>>(x);
    }
    {
        dim3 grid(25, 6, BATCH);     // (n-tile128, m-tile128, batch)
        gemm_mma_kernel<<<grid, 256, S_TOTAL>>>();
    }
    {
        dim3 grid(14, 8, BATCH);     // (bands, f, b)
        epi_kernel<<<grid, 256, E_BYTES>>>(gn_gamma, gn_beta, w2, b2, out);
    }
}